// round 17
// baseline (speedup 1.0000x reference)
#include <cuda_runtime.h>
#include <cuda_fp16.h>
#include <math.h>
#include <stdint.h>

// ============================================================================
// MultiSizeProjHead — single persistent mega-kernel (gemm1 + head fused via
// atomic work queue + per-sample dependency counters).
// R17 = R16 tile bodies (64x32 warp tiles, 2 CTAs/SM, KC=64, fp16 1-term,
// weights x256) with gemm1 tiles (sample-major) followed by head tiles;
// head pass-1 spins on its sample's 32 gemm1 tiles (threadFenceReduction idiom).
// ============================================================================
#define EMBED   1024
#define INTER   4096
#define SBASE   672
#define OUTD    21
#define NSAMP   256
#define PTOK    128
#define MROWS   (NSAMP * PTOK)
#define TTOT    2520        // 168 + 336 + 672 + 1344

#define KC       64                  // K per SMEM stage
#define TSTRIDE  144                 // bytes per smem row: 64 fp16 + 16 pad
#define TILE_B   (128 * TSTRIDE)     // 18432 bytes per 128x64 tile
#define STAGE_B  (2 * TILE_B)        // A, B = 36864
#define SMEM_TOTAL (2 * STAGE_B)     // double buffered: 73728 B

#define WSCALE   256.0f
#define INVWS    0.00390625f         // 1/256
#define NPERS    296                 // persistent CTAs (2 x 148)
#define NGEMM    (NSAMP * 32)        // 8192 gemm1 tiles (32 N-blocks / sample)

__device__ __constant__ int c_T[4]    = {168, 336, 672, 1344};
__device__ __constant__ int c_Toff[4] = {0, 168, 504, 1176};

// ---------------- device scratch (no runtime allocation allowed) -----------
__device__ __half g_xf [(size_t)MROWS * EMBED];     // x, fp16
__device__ __half g_wi [(size_t)INTER * EMBED];     // W_in*256, fp16
__device__ __half g_xsf[(size_t)MROWS * INTER];     // xs, fp16
__device__ __half g_w2 [(size_t)TTOT * INTER];      // interp W_shared^T *256, t-major
__device__ __half g_wr [(size_t)TTOT * EMBED];      // interp W_res^T *256, t-major
__device__ float g_b2[TTOT];
__device__ float g_br[TTOT];
__device__ int   g_ctr;                             // work-queue counter
__device__ int   g_cnt[NSAMP];                      // completed gemm1 tiles / sample

// ---------------- portable PTX helpers -------------------------------------
__device__ __forceinline__ uint32_t smem_to_u32(const void* p) {
    uint32_t a;
    asm("{ .reg .u64 t; cvta.to.shared.u64 t, %1; cvt.u32.u64 %0, t; }" : "=r"(a) : "l"(p));
    return a;
}
__device__ __forceinline__ void cp_async16(uint32_t dst, const void* src, uint32_t src_bytes) {
    asm volatile("cp.async.cg.shared.global [%0], [%1], 16, %2;"
                 :: "r"(dst), "l"(src), "r"(src_bytes) : "memory");
}
#define CP_COMMIT() asm volatile("cp.async.commit_group;" ::: "memory")
#define CP_WAIT0()  asm volatile("cp.async.wait_group 0;" ::: "memory")

__device__ __forceinline__ void ldsm_x4(uint32_t* r, uint32_t addr) {
    asm volatile("ldmatrix.sync.aligned.m8n8.x4.shared.b16 {%0,%1,%2,%3}, [%4];"
                 : "=r"(r[0]), "=r"(r[1]), "=r"(r[2]), "=r"(r[3]) : "r"(addr));
}
__device__ __forceinline__ void mma16816(float* c, const uint32_t* a, uint32_t b0, uint32_t b1) {
    asm volatile("mma.sync.aligned.m16n8k16.row.col.f32.f16.f16.f32 "
                 "{%0,%1,%2,%3}, {%4,%5,%6,%7}, {%8,%9}, {%0,%1,%2,%3};"
                 : "+f"(c[0]), "+f"(c[1]), "+f"(c[2]), "+f"(c[3])
                 : "r"(a[0]), "r"(a[1]), "r"(a[2]), "r"(a[3]), "r"(b0), "r"(b1));
}
__device__ __forceinline__ uint32_t pack2h(__half a, __half b) {
    return (uint32_t)__half_as_ushort(a) | ((uint32_t)__half_as_ushort(b) << 16);
}
__device__ __forceinline__ uint4 cvt8(float4 a, float4 b, float s) {
    uint4 r;
    r.x = pack2h(__float2half_rn(a.x * s), __float2half_rn(a.y * s));
    r.y = pack2h(__float2half_rn(a.z * s), __float2half_rn(a.w * s));
    r.z = pack2h(__float2half_rn(b.x * s), __float2half_rn(b.y * s));
    r.w = pack2h(__float2half_rn(b.z * s), __float2half_rn(b.w * s));
    return r;
}

// async-load one 128x64 fp16 tile (rows padded to 144B); rows >= vrows zero-fill
__device__ __forceinline__ void load_tile_async(uint32_t sdst, const __half* __restrict__ src,
                                                long row0, long stride, int k0, int tid, int vrows) {
    const int r0 = tid >> 3, c8 = tid & 7;
    const __half* p = src + (row0 + r0) * stride + k0 + (c8 << 3);
    const __half* const pSafe = src + row0 * stride + k0 + (c8 << 3);
    uint32_t d = sdst + (uint32_t)(r0 * TSTRIDE + c8 * 16);
#pragma unroll
    for (int i = 0; i < 4; i++) {
        const bool ok = (r0 + i * 32) < vrows;
        cp_async16(d, ok ? p : pSafe, ok ? 16u : 0u);
        p += 32 * stride;
        d += 32 * TSTRIDE;
    }
}

// one KC=64 stage of 1-term MMA: acc += A*B   (warp tile 64x32)
__device__ __forceinline__ void mma_stage(uint32_t base, int lane, int warp_m, int warp_n,
                                          float acc[4][4][4]) {
    const int lr = lane & 7, lg = lane >> 3;
    const int rowSel = ((lg & 1) << 3) + lr;
    const int colHalf = (lg >> 1) << 3;
    const uint32_t aBase = base + (uint32_t)((warp_m * 64 + rowSel) * TSTRIDE + colHalf * 2);
    const uint32_t bBase = base + TILE_B + (uint32_t)((warp_n * 32 + rowSel) * TSTRIDE + colHalf * 2);
#pragma unroll
    for (int k16 = 0; k16 < KC; k16 += 16) {
        const uint32_t colOff = (uint32_t)(k16 * 2);
        uint32_t a[4][4], b[2][4];
#pragma unroll
        for (int i = 0; i < 4; i++)
            ldsm_x4(a[i], aBase + (uint32_t)(i * 16 * TSTRIDE) + colOff);
#pragma unroll
        for (int jj = 0; jj < 2; jj++)
            ldsm_x4(b[jj], bBase + (uint32_t)(jj * 16 * TSTRIDE) + colOff);
#pragma unroll
        for (int i = 0; i < 4; i++)
#pragma unroll
            for (int j = 0; j < 4; j++)
                mma16816(acc[i][j], a[i], b[j >> 1][j & 1], b[j >> 1][(j & 1) + 2]);
    }
}

// ---------------- vectorized prep: 8 contiguous elements per thread --------
__device__ __forceinline__ void interp_coef(int tg, int& i0, int& i1, float& lam) {
    const int s = (tg < 168) ? 0 : (tg < 504) ? 1 : (tg < 1176) ? 2 : 3;
    const int t = tg - c_Toff[s];
    const float scale = (float)SBASE / (float)c_T[s];
    float src = fmaxf(((float)t + 0.5f) * scale - 0.5f, 0.0f);
    i0 = (int)src;
    if (i0 > SBASE - 1) i0 = SBASE - 1;
    i1 = min(i0 + 1, SBASE - 1);
    lam = src - (float)i0;
}
__device__ __forceinline__ float4 mix4(float4 a, float4 b, float lam) {
    const float om = 1.0f - lam;
    return make_float4(a.x * om + b.x * lam, a.y * om + b.y * lam,
                       a.z * om + b.z * lam, a.w * om + b.w * lam);
}

__global__ void prep_kernel(const float* __restrict__ x, const float* __restrict__ W_in,
                            const float* __restrict__ Ws, const float* __restrict__ bs,
                            const float* __restrict__ Wr, const float* __restrict__ brs) {
    const long i = blockIdx.x * (long)blockDim.x + threadIdx.x;
    if (i < NSAMP + 1) {        // reset queue + dep counters
        if (i == 0) g_ctr = 0;
        else g_cnt[i - 1] = 0;
    }
    const long nx8 = (long)MROWS * EMBED / 8;
    const long nw8 = (long)INTER * EMBED / 8;
    const long n28 = (long)TTOT * INTER / 8;
    const long nr8 = (long)TTOT * EMBED / 8;
    const long nb8 = TTOT / 8;                 // 315
    const long total = nx8 + nw8 + n28 + nr8 + 2 * nb8;
    if (i >= total) return;

    if (i < nx8) {
        const long e = i * 8;
        const float4 a = *(const float4*)(x + e);
        const float4 b = *(const float4*)(x + e + 4);
        *(uint4*)(g_xf + e) = cvt8(a, b, 1.0f);
    } else if (i < nx8 + nw8) {
        const long e = (i - nx8) * 8;
        const float4 a = *(const float4*)(W_in + e);
        const float4 b = *(const float4*)(W_in + e + 4);
        *(uint4*)(g_wi + e) = cvt8(a, b, WSCALE);
    } else if (i < nx8 + nw8 + n28) {
        const long e = (i - nx8 - nw8) * 8;
        const int t = (int)(e / INTER), k = (int)(e % INTER);
        int i0, i1; float lam;
        interp_coef(t, i0, i1, lam);
        const float4 a0 = *(const float4*)(Ws + (long)i0 * INTER + k);
        const float4 a1 = *(const float4*)(Ws + (long)i0 * INTER + k + 4);
        const float4 b0 = *(const float4*)(Ws + (long)i1 * INTER + k);
        const float4 b1 = *(const float4*)(Ws + (long)i1 * INTER + k + 4);
        *(uint4*)(g_w2 + e) = cvt8(mix4(a0, b0, lam), mix4(a1, b1, lam), WSCALE);
    } else if (i < nx8 + nw8 + n28 + nr8) {
        const long e = (i - nx8 - nw8 - n28) * 8;
        const int t = (int)(e / EMBED), k = (int)(e % EMBED);
        int i0, i1; float lam;
        interp_coef(t, i0, i1, lam);
        const float4 a0 = *(const float4*)(Wr + (long)i0 * EMBED + k);
        const float4 a1 = *(const float4*)(Wr + (long)i0 * EMBED + k + 4);
        const float4 b0 = *(const float4*)(Wr + (long)i1 * EMBED + k);
        const float4 b1 = *(const float4*)(Wr + (long)i1 * EMBED + k + 4);
        *(uint4*)(g_wr + e) = cvt8(mix4(a0, b0, lam), mix4(a1, b1, lam), WSCALE);
    } else if (i < nx8 + nw8 + n28 + nr8 + nb8) {
        const int t0 = (int)(i - nx8 - nw8 - n28 - nr8) * 8;
#pragma unroll
        for (int u = 0; u < 8; u++) {
            int i0, i1; float lam;
            interp_coef(t0 + u, i0, i1, lam);
            g_b2[t0 + u] = bs[i0] * (1.0f - lam) + bs[i1] * lam;
        }
    } else {
        const int t0 = (int)(i - nx8 - nw8 - n28 - nr8 - nb8) * 8;
#pragma unroll
        for (int u = 0; u < 8; u++) {
            int i0, i1; float lam;
            interp_coef(t0 + u, i0, i1, lam);
            g_br[t0 + u] = brs[i0] * (1.0f - lam) + brs[i1] * lam;
        }
    }
}

// ---------------- persistent mega-kernel: gemm1 tiles then head tiles -------
__global__ void __launch_bounds__(256, 2)
mega_kernel(const int* __restrict__ psz, const float* __restrict__ b_in,
            float* __restrict__ out, int max_dim, int ntiles_total) {
    extern __shared__ char smem[];
    __shared__ int s_w;
    const uint32_t sb = smem_to_u32(smem);
    const int tid = threadIdx.x;
    const int lane = tid & 31, wid = tid >> 5;
    const int warp_m = wid >> 2, warp_n = wid & 3;
    const int r0 = lane >> 2;
    const int c0 = (lane & 3) * 2;

    while (true) {
        __syncthreads();                       // smem + s_w reuse safe
        if (tid == 0) s_w = atomicAdd(&g_ctr, 1);
        __syncthreads();
        const int w = s_w;
        if (w >= ntiles_total) break;

        if (w < NGEMM) {
            // ================= gemm1 tile: sample n, N-block jn ============
            const int n  = w >> 5;             // sample-major: deps complete early
            const int jn = w & 31;
            const long bm = (long)n * 128;
            const long bn = (long)jn * 128;

            float acc[4][4][4];
#pragma unroll
            for (int i = 0; i < 4; i++)
#pragma unroll
                for (int j = 0; j < 4; j++)
#pragma unroll
                    for (int e = 0; e < 4; e++) acc[i][j][e] = 0.0f;

            load_tile_async(sb,          g_xf, bm, EMBED, 0, tid, 128);
            load_tile_async(sb + TILE_B, g_wi, bn, EMBED, 0, tid, 128);
            CP_COMMIT();
            const int nK = EMBED / KC;
            for (int ks = 0; ks < nK; ks++) {
                CP_WAIT0();
                __syncthreads();
                if (ks + 1 < nK) {
                    const uint32_t base = sb + ((ks + 1) & 1) * STAGE_B;
                    const int k0 = (ks + 1) * KC;
                    load_tile_async(base,          g_xf, bm, EMBED, k0, tid, 128);
                    load_tile_async(base + TILE_B, g_wi, bn, EMBED, k0, tid, 128);
                    CP_COMMIT();
                }
                mma_stage(sb + (ks & 1) * STAGE_B, lane, warp_m, warp_n, acc);
            }

            // epilogue: acc/256 + b_in -> fp16
#pragma unroll
            for (int i = 0; i < 4; i++) {
                const long rowA = bm + warp_m * 64 + i * 16 + r0;
                const long rowB = rowA + 8;
#pragma unroll
                for (int j = 0; j < 4; j++) {
                    const long col = bn + warp_n * 32 + j * 8 + c0;
                    const float bi0 = b_in[col], bi1 = b_in[col + 1];
                    *(uint32_t*)(g_xsf + rowA * INTER + col) =
                        pack2h(__float2half_rn(acc[i][j][0] * INVWS + bi0),
                               __float2half_rn(acc[i][j][1] * INVWS + bi1));
                    *(uint32_t*)(g_xsf + rowB * INTER + col) =
                        pack2h(__float2half_rn(acc[i][j][2] * INVWS + bi0),
                               __float2half_rn(acc[i][j][3] * INVWS + bi1));
                }
            }
            // publish (threadFenceReduction idiom)
            __threadfence();
            __syncthreads();
            if (tid == 0) atomicAdd(&g_cnt[n], 1);
            continue;
        }

        // ================= head tile: sample n, t-block tb ==================
        const int w2 = w - NGEMM;
        const int ntb = (max_dim + 127) >> 7;
        const int n  = w2 / ntb;               // sample-major: matches dep order
        const int t0 = (w2 % ntb) * 128;

        const int ps = psz[n];
        const int T = ps * OUTD;
        const int s4 = (ps == 8) ? 0 : (ps == 16) ? 1 : (ps == 32) ? 2 : 3;
        const int toff = c_Toff[s4];
        float* outBase = out + (size_t)n * PTOK * max_dim;

        if (t0 >= T) {  // zero-pad tile — no dependency
            const int colq = min(128, max_dim - t0) >> 2;
            const float4 z = make_float4(0.f, 0.f, 0.f, 0.f);
            for (int idx = tid; idx < PTOK * colq; idx += 256) {
                const int r = idx / colq, c = idx % colq;
                *reinterpret_cast<float4*>(outBase + (size_t)r * max_dim + t0 + c * 4) = z;
            }
            continue;
        }

        // wait for this sample's 32 gemm1 tiles
        if (tid == 0) {
            while (atomicAdd(&g_cnt[n], 0) < 32) __nanosleep(200);
        }
        __syncthreads();

        const int tmax = min(T - t0, 128);
        const bool active = (warp_n * 32 < tmax);
        const long arow = (long)n * PTOK;
        const long brow = (long)toff + t0;

        float acc[4][4][4];
#pragma unroll
        for (int i = 0; i < 4; i++)
#pragma unroll
            for (int j = 0; j < 4; j++)
#pragma unroll
                for (int e = 0; e < 4; e++) acc[i][j][e] = 0.0f;

        // ---- pass 1: lin = xs @ w2_seg^T  (K = 4096) ----
        load_tile_async(sb,          g_xsf, arow, INTER, 0, tid, 128);
        load_tile_async(sb + TILE_B, g_w2,  brow, INTER, 0, tid, tmax);
        CP_COMMIT();
        const int nK1 = INTER / KC;
        for (int ks = 0; ks < nK1; ks++) {
            CP_WAIT0();
            __syncthreads();
            if (ks + 1 < nK1) {
                const uint32_t base = sb + ((ks + 1) & 1) * STAGE_B;
                const int k0 = (ks + 1) * KC;
                load_tile_async(base,          g_xsf, arow, INTER, k0, tid, 128);
                load_tile_async(base + TILE_B, g_w2,  brow, INTER, k0, tid, tmax);
                CP_COMMIT();
            }
            if (active)
                mma_stage(sb + (ks & 1) * STAGE_B, lane, warp_m, warp_n, acc);
        }

        // ---- silu(acc/256 + b2), rescaled x256 for in-place pass 2 ----
        if (active) {
#pragma unroll
            for (int j = 0; j < 4; j++) {
                const int col = t0 + warp_n * 32 + j * 8 + c0;
                const float b20 = (col     < T) ? g_b2[toff + col]     : 0.0f;
                const float b21 = (col + 1 < T) ? g_b2[toff + col + 1] : 0.0f;
#pragma unroll
                for (int i = 0; i < 4; i++) {
                    float v;
                    v = acc[i][j][0] * INVWS + b20; acc[i][j][0] = v / (1.0f + __expf(-v)) * WSCALE;
                    v = acc[i][j][1] * INVWS + b21; acc[i][j][1] = v / (1.0f + __expf(-v)) * WSCALE;
                    v = acc[i][j][2] * INVWS + b20; acc[i][j][2] = v / (1.0f + __expf(-v)) * WSCALE;
                    v = acc[i][j][3] * INVWS + b21; acc[i][j][3] = v / (1.0f + __expf(-v)) * WSCALE;
                }
            }
        }

        // ---- pass 2: acc += x @ (wr*256)_seg^T  (K = 1024) ----
        load_tile_async(sb,          g_xf, arow, EMBED, 0, tid, 128);
        load_tile_async(sb + TILE_B, g_wr, brow, EMBED, 0, tid, tmax);
        CP_COMMIT();
        const int nK2 = EMBED / KC;
        for (int ks = 0; ks < nK2; ks++) {
            CP_WAIT0();
            __syncthreads();
            if (ks + 1 < nK2) {
                const uint32_t base = sb + ((ks + 1) & 1) * STAGE_B;
                const int k0 = (ks + 1) * KC;
                load_tile_async(base,          g_xf, arow, EMBED, k0, tid, 128);
                load_tile_async(base + TILE_B, g_wr, brow, EMBED, k0, tid, tmax);
                CP_COMMIT();
            }
            if (active)
                mma_stage(sb + (ks & 1) * STAGE_B, lane, warp_m, warp_n, acc);
        }

        // ---- store: acc/256 + br (cols < T), zeros to max_dim ----
#pragma unroll
        for (int i = 0; i < 4; i++) {
            const int rowA = warp_m * 64 + i * 16 + r0;
#pragma unroll
            for (int j = 0; j < 4; j++) {
                const int col = t0 + warp_n * 32 + j * 8 + c0;
                if (col >= max_dim) continue;
                float2 v0, v1;
                if (col < T) {
                    const float br0 = g_br[toff + col], br1 = g_br[toff + col + 1];
                    v0 = make_float2(acc[i][j][0] * INVWS + br0, acc[i][j][1] * INVWS + br1);
                    v1 = make_float2(acc[i][j][2] * INVWS + br0, acc[i][j][3] * INVWS + br1);
                } else {
                    v0 = make_float2(0.f, 0.f);
                    v1 = v0;
                }
                *reinterpret_cast<float2*>(outBase + (size_t)rowA * max_dim + col) = v0;
                *reinterpret_cast<float2*>(outBase + (size_t)(rowA + 8) * max_dim + col) = v1;
            }
        }
    }
}

// ----------------------------------------------------------------------------
extern "C" void kernel_launch(void* const* d_in, const int* in_sizes, int n_in,
                              void* d_out, int out_size)
{
    const float* x     = (const float*)d_in[0];
    const int*   psz   = (const int*)d_in[1];
    const float* W_in  = (const float*)d_in[2];
    const float* b_in  = (const float*)d_in[3];
    const float* W_sh  = (const float*)d_in[4];
    const float* b_sh  = (const float*)d_in[5];
    const float* W_res = (const float*)d_in[6];
    const float* b_res = (const float*)d_in[7];
    float* out = (float*)d_out;

    const int max_dim = out_size / (NSAMP * PTOK);
    const int ntb = (max_dim + 127) / 128;
    const int ntiles_total = NGEMM + ntb * NSAMP;

    cudaFuncSetAttribute(mega_kernel, cudaFuncAttributeMaxDynamicSharedMemorySize, SMEM_TOTAL);

    // 1) vectorized prep (also resets queue + dep counters)
    {
        const long total = ((long)MROWS * EMBED + (long)INTER * EMBED
                          + (long)TTOT * INTER + (long)TTOT * EMBED + 2L * TTOT) / 8;
        prep_kernel<<<(unsigned)((total + 255) / 256), 256>>>(x, W_in, W_sh, b_sh, W_res, b_res);
    }
    // 2) persistent fused gemm1 + heads (atomic queue, per-sample deps)
    mega_kernel<<<NPERS, 256, SMEM_TOTAL>>>(psz, b_in, out, max_dim, ntiles_total);
}